// round 11
// baseline (speedup 1.0000x reference)
#include <cuda_runtime.h>
#include <math.h>

// Problem dims
#define S_ 2048
#define B_ 64
#define I_ 256
#define H_ 512
#define ROWS_ (S_ * B_)          // 131072
#define BH_ (B_ * H_)

// ---------------- scratch (no cudaMalloc allowed) ----------------
__device__ float g_buf0[(size_t)S_ * BH_];       // xb0 from projection
__device__ float2 g_pack[2][B_][H_];             // (y0,y1) exchange ring (512KB, L2)
__device__ unsigned g_ctr[256];                  // per-bgroup arrival ctr @ bg*32
__device__ unsigned g_flag[256];                 // per-bgroup release flag @ bg*32
// NOTE: ctr/flag are MONOTONIC across launches (graph replays); each launch
// reads its base at entry. No init kernel -> 2 launches/call (ncu -s 5 hits rnn).

// ---------------- packed f32x2 FMA ----------------
__device__ __forceinline__ void fma2(float2& d, float ax, float ay,
                                     float bx, float by) {
    asm volatile(
        "{\n\t"
        ".reg .b64 ra, rb, rd;\n\t"
        "mov.b64 ra, {%2, %3};\n\t"
        "mov.b64 rb, {%4, %5};\n\t"
        "mov.b64 rd, {%0, %1};\n\t"
        "fma.rn.f32x2 rd, ra, rb, rd;\n\t"
        "mov.b64 {%0, %1}, rd;\n\t"
        "}"
        : "+f"(d.x), "+f"(d.y)
        : "f"(ax), "f"(ay), "f"(bx), "f"(by));
}

__device__ __forceinline__ unsigned su32(const void* p) {
    return (unsigned)__cvta_generic_to_shared(p);
}
__device__ __forceinline__ void cp16(unsigned dst, const void* src) {
    asm volatile("cp.async.cg.shared.global [%0], [%1], 16;" :: "r"(dst), "l"(src));
}
#define CP_COMMIT() asm volatile("cp.async.commit_group;" ::: "memory")
#define CP_WAIT0()  asm volatile("cp.async.wait_group 0;" ::: "memory")

// ---------------- projection GEMM (layer 0 only) ----------------
#define TM 64
#define TN 64
#define KC 64
#define SAST 66

__global__ void __launch_bounds__(256) proj_kernel(
    const float* __restrict__ A,
    const float* __restrict__ W,
    const int*   __restrict__ Wmask,
    const float* __restrict__ bias1,
    const float* __restrict__ bias2,
    int K)
{
    __shared__ float SA[TM * SAST];
    __shared__ float SW[TN * SAST];

    float* C = g_buf0;
    const int m0 = blockIdx.x * TM;
    const int n0 = blockIdx.y * TN;
    const int tid = threadIdx.x;
    const int tx = tid & 15;
    const int ty = tid >> 4;

    float2 acc[4][4];
#pragma unroll
    for (int i = 0; i < 4; i++)
#pragma unroll
        for (int j = 0; j < 4; j++) acc[i][j] = make_float2(0.f, 0.f);

    for (int kc = 0; kc < K; kc += KC) {
#pragma unroll
        for (int t = tid; t < TM * 16; t += 256) {
            int r = t >> 4, q = t & 15;
            float4 v = *(const float4*)&A[(size_t)(m0 + r) * K + kc + 4 * q];
            int o = r * SAST + 4 * q;
            *(float2*)&SA[o]     = make_float2(v.x, v.y);
            *(float2*)&SA[o + 2] = make_float2(v.z, v.w);
        }
#pragma unroll
        for (int t = tid; t < TN * 16; t += 256) {
            int r = t >> 4, q = t & 15;
            size_t g = (size_t)(n0 + r) * K + kc + 4 * q;
            float4 v = *(const float4*)&W[g];
            int4  mm = *(const int4*)&Wmask[g];
            int o = r * SAST + 4 * q;
            SW[o]     = v.x * (float)mm.x;
            SW[o + 1] = v.y * (float)mm.y;
            SW[o + 2] = v.z * (float)mm.z;
            SW[o + 3] = v.w * (float)mm.w;
        }
        __syncthreads();

#pragma unroll 8
        for (int k = 0; k < KC; k += 2) {
            float2 a[4], w[4];
#pragma unroll
            for (int i = 0; i < 4; i++) a[i] = *(float2*)&SA[(ty + 16 * i) * SAST + k];
#pragma unroll
            for (int j = 0; j < 4; j++) w[j] = *(float2*)&SW[(tx + 16 * j) * SAST + k];
#pragma unroll
            for (int i = 0; i < 4; i++)
#pragma unroll
                for (int j = 0; j < 4; j++)
                    fma2(acc[i][j], a[i].x, a[i].y, w[j].x, w[j].y);
        }
        __syncthreads();
    }

#pragma unroll
    for (int j = 0; j < 4; j++) {
        int n = n0 + tx + 16 * j;
        float bb = bias1[n] + bias2[n];
#pragma unroll
        for (int i = 0; i < 4; i++) {
            int m = m0 + ty + 16 * i;
            C[(size_t)m * H_ + n] = acc[i][j].x + acc[i][j].y + bb;
        }
    }
}

// ---------------- fused 2-layer recurrence -------------------------------
// round t: L0 computes y0[t] (t<S), L1 computes y1[t-1] (t>=1).
// 128 CTAs = 8 bg x 16 hg; CTA = 8 rows x 32 cols; 256 threads:
// col = tid&31, ks = tid>>5 (8 x 64-k slices); weights (3x64 f32) in regs.
// Exchange: packed (y0,y1) ring; sync: R8 scheme (atomic ctr + release flag,
// ALL threads spin on the flag), monotonic across launches.
#define NCTA 128
#define RTH  256
#define GSZ  16
#define BROWS 8
// smem (floats): hs pairs [8][512]x2 = 8192; red float4[8][256] = 8192
#define HS_OFF   0
#define RED_OFF  8192
#define SMEM_FLOATS 16384
#define RNN_SMEM_BYTES (SMEM_FLOATS * 4)   // 65536 B

__global__ void __launch_bounds__(RTH, 1) rnn_pipe_kernel(
    const float* __restrict__ Whh0, const int* __restrict__ m_hh0,
    const float* __restrict__ Wih1, const int* __restrict__ m_ih1,
    const float* __restrict__ Whh1, const int* __restrict__ m_hh1,
    const float* __restrict__ b_ih1, const float* __restrict__ b_hh1,
    float* __restrict__ out)
{
    extern __shared__ float smem[];
    float* hs  = smem + HS_OFF;        // [8][512] float2 pairs
    float* red = smem + RED_OFF;       // [8][256] float4

    const int bg = blockIdx.x >> 4;   // 0..7
    const int hg = blockIdx.x & 15;   // 0..15
    const int b0 = bg * BROWS;
    const int h0 = hg * 32;
    const int tid = threadIdx.x;
    const int col = tid & 31;         // col this thread's k-partials serve
    const int ks  = tid >> 5;         // 0..7, 64-k slice
    const int k0  = ks * 64;

    unsigned* ctr  = &g_ctr[bg * 32];
    unsigned* flag = &g_flag[bg * 32];

    // monotonic bases (previous launch's final values; stable at entry)
    unsigned base_f, base_c;
    asm volatile("ld.relaxed.gpu.global.u32 %0, [%1];" : "=r"(base_f) : "l"(flag));
    asm volatile("ld.relaxed.gpu.global.u32 %0, [%1];" : "=r"(base_c) : "l"(ctr));

    // ---- permanent register weights: 16 float4 per gemm (64 k) ----
    float4 wr0[16], wr1[16], wr2[16];
    {
        size_t ro = (size_t)(h0 + col) * H_ + k0;
#pragma unroll
        for (int q = 0; q < 16; q++) {
            float4 v; int4 mm;
            v = *(const float4*)&Whh0[ro + 4 * q];
            mm = *(const int4*)&m_hh0[ro + 4 * q];
            wr0[q] = make_float4(v.x * (float)mm.x, v.y * (float)mm.y,
                                 v.z * (float)mm.z, v.w * (float)mm.w);
            v = *(const float4*)&Wih1[ro + 4 * q];
            mm = *(const int4*)&m_ih1[ro + 4 * q];
            wr1[q] = make_float4(v.x * (float)mm.x, v.y * (float)mm.y,
                                 v.z * (float)mm.z, v.w * (float)mm.w);
            v = *(const float4*)&Whh1[ro + 4 * q];
            mm = *(const int4*)&m_hh1[ro + 4 * q];
            wr2[q] = make_float4(v.x * (float)mm.x, v.y * (float)mm.y,
                                 v.z * (float)mm.z, v.w * (float)mm.w);
        }
    }

    // output mapping: thread -> (row tid>>5, col tid&31)
    const int orow = tid >> 5;
    const int ocol = tid & 15 | (tid & 31);   // == tid & 31
    const size_t offO = (size_t)(b0 + orow) * H_ + (h0 + (tid & 31));
    float2* my_pack0 = &g_pack[0][b0 + orow][h0 + (tid & 31)];
    float2* my_pack1 = &g_pack[1][b0 + orow][h0 + (tid & 31)];
    const float bL1 = __ldg(&b_ih1[h0 + (tid & 31)]) + __ldg(&b_hh1[h0 + (tid & 31)]);
    float xv = __ldg(&g_buf0[offO]);
    (void)ocol;

    const unsigned hs_b = su32(hs);

    for (int t = 0; t <= S_; ++t) {
        float s0 = 0.f, s1 = 0.f, s2 = 0.f;

        if (t > 0) {
            // ---- wait: ALL threads spin on read-mostly flag (R8 scheme) ----
            unsigned target = base_f + (unsigned)t;
            unsigned f;
            do {
                asm volatile("ld.acquire.gpu.global.u32 %0, [%1];"
                             : "=r"(f) : "l"(flag) : "memory");
            } while (f < target);

            // ---- stage pack[(t-1)&1] rows b0..b0+7 : 32KB, one group ----
            {
                const float2* src = &g_pack[(t - 1) & 1][b0][0];
#pragma unroll
                for (int i = 0; i < 8; i++) {
                    int idx = tid + i * RTH;             // 0..2047 16B chunks
                    cp16(hs_b + (unsigned)idx * 16u, (const char*)src + idx * 16);
                }
            }
            CP_COMMIT();
            CP_WAIT0();
            __syncthreads();

            // ---- fused 3-gemm pass over 8 rows ----
#pragma unroll 2
            for (int r = 0; r < BROWS; r++) {
                const float4* ap4 = (const float4*)(hs + (r * 512 + k0) * 2);
                float2 u0 = make_float2(0.f, 0.f);
                float2 u1 = make_float2(0.f, 0.f);
                float2 u2 = make_float2(0.f, 0.f);
#pragma unroll
                for (int q = 0; q < 16; q++) {
                    float4 d0 = ap4[2 * q];       // cols 4q,4q+1: (y0,y1,y0,y1)
                    float4 d1 = ap4[2 * q + 1];   // cols 4q+2,4q+3
                    float4 w0 = wr0[q], w1 = wr1[q], w2 = wr2[q];
                    fma2(u0, d0.x, d0.z, w0.x, w0.y);
                    fma2(u0, d1.x, d1.z, w0.z, w0.w);
                    fma2(u1, d0.x, d0.z, w1.x, w1.y);
                    fma2(u1, d1.x, d1.z, w1.z, w1.w);
                    fma2(u2, d0.y, d0.w, w2.x, w2.y);
                    fma2(u2, d1.y, d1.w, w2.z, w2.w);
                }
                *(float4*)&red[(ks * 256 + r * 32 + col) * 4] =
                    make_float4(u0.x + u0.y, u1.x + u1.y, u2.x + u2.y, 0.f);
            }
            __syncthreads();

            // ---- 8-way k-slice reduction (1 output per thread) ----
#pragma unroll
            for (int k = 0; k < 8; k++) {
                float4 v = *(const float4*)&red[(k * 256 + tid) * 4];
                s0 += v.x;
                s1 += v.y;
                s2 += v.z;
            }
        }

        float y0v = 0.f, y1v = 0.f;
        if (t < S_) y0v = tanhf(s0 + xv);
        if (t > 0)  y1v = tanhf(s1 + s2 + bL1);

        if (t == S_) {
            out[offO] = y1v;                 // final y1[S-1] straight to output
        } else {
            // publish (y0[t], y1[t-1]) to ring slot t&1 (y1v==0 at t==0: h0)
            float2* dst = (t & 1) ? my_pack1 : my_pack0;
            *dst = make_float2(y0v, y1v);
            if (t + 1 < S_)
                xv = __ldg(&g_buf0[(size_t)(t + 1) * BH_ + offO]);

            // arrive: atomic on ctr line; last arriver releases the flag line
            __syncthreads();
            if (tid == 0) {
                unsigned old;
                asm volatile("atom.acq_rel.gpu.global.add.u32 %0, [%1], 1;"
                             : "=r"(old) : "l"(ctr) : "memory");
                if (old == base_c + (unsigned)((t + 1) * GSZ - 1)) {
                    asm volatile("st.release.gpu.global.u32 [%0], %1;"
                                 :: "l"(flag), "r"(base_f + (unsigned)(t + 1))
                                 : "memory");
                }
            }
        }
    }
}

// ---------------- launch ----------------
extern "C" void kernel_launch(void* const* d_in, const int* in_sizes, int n_in,
                              void* d_out, int out_size) {
    const float* x       = (const float*)d_in[0];
    const float* W_ih0   = (const float*)d_in[1];
    const float* W_hh0   = (const float*)d_in[2];
    const float* b_ih0   = (const float*)d_in[3];
    const float* b_hh0   = (const float*)d_in[4];
    const float* W_ih1   = (const float*)d_in[5];
    const float* W_hh1   = (const float*)d_in[6];
    const float* b_ih1   = (const float*)d_in[7];
    const float* b_hh1   = (const float*)d_in[8];
    const int*   m_ih0   = (const int*)d_in[9];
    const int*   m_hh0   = (const int*)d_in[10];
    const int*   m_ih1   = (const int*)d_in[11];
    const int*   m_hh1   = (const int*)d_in[12];
    float* out = (float*)d_out;

    static bool attr_set = false;
    if (!attr_set) {
        cudaFuncSetAttribute(rnn_pipe_kernel,
                             cudaFuncAttributeMaxDynamicSharedMemorySize,
                             RNN_SMEM_BYTES);
        attr_set = true;
    }

    // 2 launches per call => ncu -s 5 -c 1 captures the rnn kernel
    dim3 pgrid(ROWS_ / TM, H_ / TN);
    proj_kernel<<<pgrid, 256>>>(x, W_ih0, m_ih0, b_ih0, b_hh0, I_);

    rnn_pipe_kernel<<<NCTA, RTH, RNN_SMEM_BYTES>>>(
        W_hh0, m_hh0, W_ih1, m_ih1, W_hh1, m_hh1, b_ih1, b_hh1, out);
}

// round 13
// speedup vs baseline: 1.2048x; 1.2048x over previous
#include <cuda_runtime.h>
#include <math.h>

// Problem dims
#define S_ 2048
#define B_ 64
#define I_ 256
#define H_ 512
#define ROWS_ (S_ * B_)          // 131072
#define BH_ (B_ * H_)

// ---------------- scratch (no cudaMalloc allowed) ----------------
__device__ float g_buf0[(size_t)S_ * BH_];   // xb0 -> y0 (in place)
__device__ float g_buf1[(size_t)S_ * BH_];   // y1
__device__ float g_zero[16 * H_];            // stays zero (bss)
__device__ unsigned g_ctr[256];              // per-bgroup counter at bg*32
__device__ unsigned g_flag[256];             // per-bgroup release flag at bg*32

// ---------------- packed f32x2 FMA ----------------
__device__ __forceinline__ void fma2(float2& d, float ax, float ay,
                                     float bx, float by) {
    asm volatile(
        "{\n\t"
        ".reg .b64 ra, rb, rd;\n\t"
        "mov.b64 ra, {%2, %3};\n\t"
        "mov.b64 rb, {%4, %5};\n\t"
        "mov.b64 rd, {%0, %1};\n\t"
        "fma.rn.f32x2 rd, ra, rb, rd;\n\t"
        "mov.b64 {%0, %1}, rd;\n\t"
        "}"
        : "+f"(d.x), "+f"(d.y)
        : "f"(ax), "f"(ay), "f"(bx), "f"(by));
}
__device__ __forceinline__ void fma4(float2& acc, float4 a, float4 w) {
    fma2(acc, a.x, a.y, w.x, w.y);
    fma2(acc, a.z, a.w, w.z, w.w);
}

__device__ __forceinline__ unsigned su32(const void* p) {
    return (unsigned)__cvta_generic_to_shared(p);
}
__device__ __forceinline__ void cp16(unsigned dst, const void* src) {
    asm volatile("cp.async.cg.shared.global [%0], [%1], 16;" :: "r"(dst), "l"(src));
}
#define CP_COMMIT() asm volatile("cp.async.commit_group;" ::: "memory")
#define CP_WAIT0()  asm volatile("cp.async.wait_group 0;" ::: "memory")
#define CP_WAIT1()  asm volatile("cp.async.wait_group 1;" ::: "memory")

// ---------------- counter init (graph-replay safe reset) ----------------
__global__ void init_ctrs_kernel() {
    int i = threadIdx.x;
    g_ctr[i] = 0u;
    g_flag[i] = 0u;
}

// ---------------- projection GEMM (layer 0 only) ----------------
#define TM 64
#define TN 64
#define KC 64
#define SAST 66

__global__ void __launch_bounds__(256) proj_kernel(
    const float* __restrict__ A,
    const float* __restrict__ W,
    const int*   __restrict__ Wmask,
    const float* __restrict__ bias1,
    const float* __restrict__ bias2,
    int K)
{
    __shared__ float SA[TM * SAST];
    __shared__ float SW[TN * SAST];

    float* C = g_buf0;
    const int m0 = blockIdx.x * TM;
    const int n0 = blockIdx.y * TN;
    const int tid = threadIdx.x;
    const int tx = tid & 15;
    const int ty = tid >> 4;

    float2 acc[4][4];
#pragma unroll
    for (int i = 0; i < 4; i++)
#pragma unroll
        for (int j = 0; j < 4; j++) acc[i][j] = make_float2(0.f, 0.f);

    for (int kc = 0; kc < K; kc += KC) {
#pragma unroll
        for (int t = tid; t < TM * 16; t += 256) {
            int r = t >> 4, q = t & 15;
            float4 v = *(const float4*)&A[(size_t)(m0 + r) * K + kc + 4 * q];
            int o = r * SAST + 4 * q;
            *(float2*)&SA[o]     = make_float2(v.x, v.y);
            *(float2*)&SA[o + 2] = make_float2(v.z, v.w);
        }
#pragma unroll
        for (int t = tid; t < TN * 16; t += 256) {
            int r = t >> 4, q = t & 15;
            size_t g = (size_t)(n0 + r) * K + kc + 4 * q;
            float4 v = *(const float4*)&W[g];
            int4  mm = *(const int4*)&Wmask[g];
            int o = r * SAST + 4 * q;
            SW[o]     = v.x * (float)mm.x;
            SW[o + 1] = v.y * (float)mm.y;
            SW[o + 2] = v.z * (float)mm.z;
            SW[o + 3] = v.w * (float)mm.w;
        }
        __syncthreads();

#pragma unroll 8
        for (int k = 0; k < KC; k += 2) {
            float2 a[4], w[4];
#pragma unroll
            for (int i = 0; i < 4; i++) a[i] = *(float2*)&SA[(ty + 16 * i) * SAST + k];
#pragma unroll
            for (int j = 0; j < 4; j++) w[j] = *(float2*)&SW[(tx + 16 * j) * SAST + k];
#pragma unroll
            for (int i = 0; i < 4; i++)
#pragma unroll
                for (int j = 0; j < 4; j++)
                    fma2(acc[i][j], a[i].x, a[i].y, w[j].x, w[j].y);
        }
        __syncthreads();
    }

#pragma unroll
    for (int j = 0; j < 4; j++) {
        int n = n0 + tx + 16 * j;
        float bb = bias1[n] + bias2[n];
#pragma unroll
        for (int i = 0; i < 4; i++) {
            int m = m0 + ty + 16 * i;
            C[(size_t)m * H_ + n] = acc[i][j].x + acc[i][j].y + bb;
        }
    }
}

// ---------------- fused 2-layer recurrence (R8 skeleton, direct out) ------
// round t: L0 computes y0[t] (t<S), L1 computes y1[t-1] (t>=1).
// 128 CTAs = 8 bg x 16 hg; CTA = 8 rows x 32 cols; 256 threads:
// col = tid&31, ks = tid>>5 (8 x 64-k slices); weights (3x64 f32) in regs.
// Sync: per-bgroup atomic ctr + release flag; ALL threads spin on the flag.
#define NCTA 128
#define RTH  256
#define GSZ  16
#define BROWS 8
#define HS0_OFF 0                    // [8][512]
#define HS1_OFF 4096                 // [8][512]
#define RED01_OFF 8192               // [8][256] float2
#define RED2_OFF 12288               // [8][256] float
#define SMEM_FLOATS 14336
#define RNN_SMEM_BYTES (SMEM_FLOATS * 4)   // 57344 B

__global__ void __launch_bounds__(RTH, 1) rnn_pipe_kernel(
    const float* __restrict__ Whh0, const int* __restrict__ m_hh0,
    const float* __restrict__ Wih1, const int* __restrict__ m_ih1,
    const float* __restrict__ Whh1, const int* __restrict__ m_hh1,
    const float* __restrict__ b_ih1, const float* __restrict__ b_hh1,
    float* __restrict__ out)
{
    extern __shared__ float smem[];
    float* hs0   = smem + HS0_OFF;
    float* hs1   = smem + HS1_OFF;
    float* red01 = smem + RED01_OFF;
    float* red2  = smem + RED2_OFF;

    const int bg = blockIdx.x >> 4;   // 0..7
    const int hg = blockIdx.x & 15;   // 0..15
    const int b0 = bg * BROWS;
    const int h0 = hg * 32;
    const int tid = threadIdx.x;
    const int col = tid & 31;         // output col within tile
    const int ks  = tid >> 5;         // 0..7, 64-k slice
    const int k0  = ks * 64;

    unsigned* ctr  = &g_ctr[bg * 32];
    unsigned* flag = &g_flag[bg * 32];

    // ---- permanent register weights: 16 float4 per gemm (64 k) ----
    float4 wr0[16], wr1[16], wr2[16];
    {
        size_t ro = (size_t)(h0 + col) * H_ + k0;
#pragma unroll
        for (int q = 0; q < 16; q++) {
            float4 v; int4 mm;
            v = *(const float4*)&Whh0[ro + 4 * q];
            mm = *(const int4*)&m_hh0[ro + 4 * q];
            wr0[q] = make_float4(v.x * (float)mm.x, v.y * (float)mm.y,
                                 v.z * (float)mm.z, v.w * (float)mm.w);
            v = *(const float4*)&Wih1[ro + 4 * q];
            mm = *(const int4*)&m_ih1[ro + 4 * q];
            wr1[q] = make_float4(v.x * (float)mm.x, v.y * (float)mm.y,
                                 v.z * (float)mm.z, v.w * (float)mm.w);
            v = *(const float4*)&Whh1[ro + 4 * q];
            mm = *(const int4*)&m_hh1[ro + 4 * q];
            wr2[q] = make_float4(v.x * (float)mm.x, v.y * (float)mm.y,
                                 v.z * (float)mm.z, v.w * (float)mm.w);
        }
    }

    // output mapping: thread -> (row tid>>5, col tid&31)
    const int orow = tid >> 5;
    const int ocol = tid & 31;
    const size_t offO = (size_t)(b0 + orow) * H_ + (h0 + ocol);
    const float bL1 = __ldg(&b_ih1[h0 + ocol]) + __ldg(&b_hh1[h0 + ocol]);
    float xv = __ldg(&g_buf0[offO]);

    const unsigned hs0_b = su32(hs0);
    const unsigned hs1_b = su32(hs1);

    for (int t = 0; t <= S_; ++t) {
        float s0 = 0.f, s1 = 0.f, s2 = 0.f;

        if (t > 0) {
            // wait for step t-1 of this batch-group (all threads spin)
            unsigned f;
            do {
                asm volatile("ld.acquire.gpu.global.u32 %0, [%1];"
                             : "=r"(f) : "l"(flag) : "memory");
            } while (f < (unsigned)t);

            // stage hs0 = y0[t-1][b0..b0+8][0..512): 16KB contiguous
            {
                const float* src = g_buf0 + (size_t)(t - 1) * BH_ + (size_t)b0 * H_;
#pragma unroll
                for (int i = 0; i < 4; i++) {
                    int idx = tid + i * RTH;             // 0..1023 16B chunks
                    cp16(hs0_b + (unsigned)idx * 16u, src + (size_t)idx * 4);
                }
            }
            CP_COMMIT();
            // stage hs1 = y1[t-2] (zeros at t==1)
            {
                const float* src = (t >= 2)
                    ? g_buf1 + (size_t)(t - 2) * BH_ + (size_t)b0 * H_ : g_zero;
#pragma unroll
                for (int i = 0; i < 4; i++) {
                    int idx = tid + i * RTH;
                    cp16(hs1_b + (unsigned)idx * 16u, src + (size_t)idx * 4);
                }
            }
            CP_COMMIT();

            CP_WAIT1();              // hs0 ready
            __syncthreads();

            // gemm0 (Whh0) + gemm1 (Wih1) over hs0 rows; full-warp broadcast
#pragma unroll 2
            for (int r = 0; r < BROWS; r++) {
                const float* ap = &hs0[r * H_ + k0];
                float2 u0 = make_float2(0.f, 0.f);
                float2 u1 = make_float2(0.f, 0.f);
#pragma unroll
                for (int q = 0; q < 16; q++) {
                    float4 a = *(const float4*)&ap[4 * q];
                    fma4(u0, a, wr0[q]);
                    fma4(u1, a, wr1[q]);
                }
                *(float2*)&red01[(ks * 256 + r * 32 + col) * 2] =
                    make_float2(u0.x + u0.y, u1.x + u1.y);
            }

            CP_WAIT0();              // hs1 ready
            __syncthreads();

            // gemm2 (Whh1) over hs1 rows
#pragma unroll 2
            for (int r = 0; r < BROWS; r++) {
                const float* ap = &hs1[r * H_ + k0];
                float2 u2 = make_float2(0.f, 0.f);
#pragma unroll
                for (int q = 0; q < 16; q++) {
                    float4 a = *(const float4*)&ap[4 * q];
                    fma4(u2, a, wr2[q]);
                }
                red2[ks * 256 + r * 32 + col] = u2.x + u2.y;
            }
            __syncthreads();

            // 8-way k-slice reduction (1 output per thread)
#pragma unroll
            for (int k = 0; k < 8; k++) {
                float2 v = *(const float2*)&red01[(k * 256 + tid) * 2];
                s0 += v.x;
                s1 += v.y;
                s2 += red2[k * 256 + tid];
            }
        }

        if (t < S_) {
            float y0 = tanhf(s0 + xv);
            g_buf0[(size_t)t * BH_ + offO] = y0;
            if (t + 1 < S_)
                xv = __ldg(&g_buf0[(size_t)(t + 1) * BH_ + offO]);
        }
        if (t > 0) {
            float y1 = tanhf(s1 + s2 + bL1);
            if (t == S_) {
                out[offO] = y1;      // final y1[S-1] straight to output
            } else {
                g_buf1[(size_t)(t - 1) * BH_ + offO] = y1;
            }
        }

        // group barrier arrival (skip at t==S: flag S was released at t==S-1)
        if (t < S_) {
            __syncthreads();
            if (tid == 0) {
                unsigned old;
                asm volatile("atom.acq_rel.gpu.global.add.u32 %0, [%1], 1;"
                             : "=r"(old) : "l"(ctr) : "memory");
                if (old == (unsigned)((t + 1) * GSZ - 1)) {
                    asm volatile("st.release.gpu.global.u32 [%0], %1;"
                                 :: "l"(flag), "r"((unsigned)(t + 1)) : "memory");
                }
            }
        }
    }
}

// ---------------- launch ----------------
extern "C" void kernel_launch(void* const* d_in, const int* in_sizes, int n_in,
                              void* d_out, int out_size) {
    const float* x       = (const float*)d_in[0];
    const float* W_ih0   = (const float*)d_in[1];
    const float* W_hh0   = (const float*)d_in[2];
    const float* b_ih0   = (const float*)d_in[3];
    const float* b_hh0   = (const float*)d_in[4];
    const float* W_ih1   = (const float*)d_in[5];
    const float* W_hh1   = (const float*)d_in[6];
    const float* b_ih1   = (const float*)d_in[7];
    const float* b_hh1   = (const float*)d_in[8];
    const int*   m_ih0   = (const int*)d_in[9];
    const int*   m_hh0   = (const int*)d_in[10];
    const int*   m_ih1   = (const int*)d_in[11];
    const int*   m_hh1   = (const int*)d_in[12];
    float* out = (float*)d_out;

    static bool attr_set = false;
    if (!attr_set) {
        cudaFuncSetAttribute(rnn_pipe_kernel,
                             cudaFuncAttributeMaxDynamicSharedMemorySize,
                             RNN_SMEM_BYTES);
        attr_set = true;
    }

    // 3 launches/call => ncu -s 5 -c 1 lands on rnn_pipe_kernel
    init_ctrs_kernel<<<1, 256>>>();

    dim3 pgrid(ROWS_ / TM, H_ / TN);
    proj_kernel<<<pgrid, 256>>>(x, W_ih0, m_ih0, b_ih0, b_hh0, I_);

    rnn_pipe_kernel<<<NCTA, RTH, RNN_SMEM_BYTES>>>(
        W_hh0, m_hh0, W_ih1, m_ih1, W_hh1, m_hh1, b_ih1, b_hh1, out);
}